// round 3
// baseline (speedup 1.0000x reference)
#include <cuda_runtime.h>
#include <cstdint>

#define MAXN 100000
#define MAXE 1600000
#define IND 128
#define HID 64

// ---------------- scratch (device globals; no allocation allowed) ----------------
__device__ int   d_is64;
__device__ int   d_edge[2 * MAXE];          // normalized int32 edge index [2][E]
__device__ int   d_deg[MAXN];
__device__ float d_dinv[MAXN];
__device__ float d_g[(size_t)MAXN * HID];   // h * dinv[row]
__device__ float d_S[(size_t)MAXN * HID];   // accumulator (init = g, self loop)

// ---------------- threefry-2x32 (exact JAX reproduction, key = (0,42)) ------------
__device__ __forceinline__ void tf_round(unsigned& a, unsigned& b, int r) {
    a += b;
    b = __funnelshift_l(b, b, r);   // rotate-left
    b ^= a;
}

__device__ __forceinline__ void threefry2x32(unsigned k0, unsigned k1,
                                             unsigned& x0, unsigned& x1) {
    unsigned k2 = k0 ^ k1 ^ 0x1BD11BDAu;
    x0 += k0; x1 += k1;
    tf_round(x0, x1, 13); tf_round(x0, x1, 15); tf_round(x0, x1, 26); tf_round(x0, x1, 6);
    x0 += k1; x1 += k2 + 1u;
    tf_round(x0, x1, 17); tf_round(x0, x1, 29); tf_round(x0, x1, 16); tf_round(x0, x1, 24);
    x0 += k2; x1 += k0 + 2u;
    tf_round(x0, x1, 13); tf_round(x0, x1, 15); tf_round(x0, x1, 26); tf_round(x0, x1, 6);
    x0 += k0; x1 += k1 + 3u;
    tf_round(x0, x1, 17); tf_round(x0, x1, 29); tf_round(x0, x1, 16); tf_round(x0, x1, 24);
    x0 += k1; x1 += k2 + 4u;
    tf_round(x0, x1, 13); tf_round(x0, x1, 15); tf_round(x0, x1, 26); tf_round(x0, x1, 6);
    x0 += k2; x1 += k0 + 5u;
}

// Partitionable-threefry keep bit for flat element index f (JAX >= 0.4.36 default):
// counter = (hi32(f)=0, lo32(f)); bits = out0 ^ out1; keep <=> bit31 == 0.
__device__ __forceinline__ bool jax_keep(unsigned f) {
    unsigned x0 = 0u, x1 = f;
    threefry2x32(0u, 42u, x0, x1);
    return ((x0 ^ x1) >> 31) == 0u;
}

// ---------------- kernels ---------------------------------------------------------
// Detect int64 vs int32 edge_index: for int64 (values < 2^31, LE) every odd 32-bit
// word is 0. For int32 node ids, odd words are random in [0,100000).
__global__ void k_detect(const unsigned* __restrict__ p) {
    __shared__ int any;
    if (threadIdx.x == 0) any = 0;
    __syncthreads();
    if (threadIdx.x < 128) {
        unsigned v = p[1 + 2 * threadIdx.x];
        if (v != 0u) atomicExch(&any, 1);
    }
    __syncthreads();
    if (threadIdx.x == 0) d_is64 = (any == 0) ? 1 : 0;
}

__global__ void k_convert(const void* __restrict__ p, int total) {
    int i = blockIdx.x * blockDim.x + threadIdx.x;
    if (i >= total) return;
    if (d_is64)
        d_edge[i] = (int)((const long long*)p)[i];
    else
        d_edge[i] = ((const int*)p)[i];
}

__global__ void k_initdeg(int n) {
    int i = blockIdx.x * blockDim.x + threadIdx.x;
    if (i < n) d_deg[i] = 1;   // self loop
}

__global__ void k_degree(int E) {
    int e = blockIdx.x * blockDim.x + threadIdx.x;
    if (e < E) atomicAdd(&d_deg[d_edge[E + e]], 1);
}

__global__ void k_dinv(int n) {
    int i = blockIdx.x * blockDim.x + threadIdx.x;
    if (i < n) d_dinv[i] = rsqrtf((float)d_deg[i]);
}

// g = (x @ W) * dinv[row];  S = g   (self-loop init)
// block = 256 threads -> 128 rows; thread computes 4 rows x 8 cols.
__global__ __launch_bounds__(256) void k_gemm(const float* __restrict__ x,
                                              const float* __restrict__ W,
                                              int n) {
    __shared__ float sW[IND * HID];
    for (int t = threadIdx.x; t < (IND * HID) / 4; t += 256)
        ((float4*)sW)[t] = ((const float4*)W)[t];
    __syncthreads();

    int cg   = threadIdx.x & 7;      // column group: cols cg*8 .. cg*8+7
    int rl   = threadIdx.x >> 3;     // 0..31
    int row0 = blockIdx.x * 128 + rl * 4;

    const float* px[4];
#pragma unroll
    for (int i = 0; i < 4; i++) {
        int r = row0 + i; if (r >= n) r = n - 1;
        px[i] = x + (size_t)r * IND;
    }

    float acc[4][8];
#pragma unroll
    for (int i = 0; i < 4; i++)
#pragma unroll
        for (int j = 0; j < 8; j++) acc[i][j] = 0.f;

    for (int k0 = 0; k0 < IND; k0 += 4) {
        float xr[4][4];
#pragma unroll
        for (int i = 0; i < 4; i++)
            *(float4*)xr[i] = *(const float4*)(px[i] + k0);
#pragma unroll
        for (int kk = 0; kk < 4; kk++) {
            const float4* wp = (const float4*)(sW + (k0 + kk) * HID + cg * 8);
            float4 wa = wp[0], wb = wp[1];
            float w[8] = {wa.x, wa.y, wa.z, wa.w, wb.x, wb.y, wb.z, wb.w};
#pragma unroll
            for (int i = 0; i < 4; i++) {
                float xs = xr[i][kk];
#pragma unroll
                for (int j = 0; j < 8; j++) acc[i][j] += xs * w[j];
            }
        }
    }

#pragma unroll
    for (int i = 0; i < 4; i++) {
        int r = row0 + i;
        if (r >= n) break;
        float dv = d_dinv[r];
        float4 o0 = make_float4(acc[i][0] * dv, acc[i][1] * dv, acc[i][2] * dv, acc[i][3] * dv);
        float4 o1 = make_float4(acc[i][4] * dv, acc[i][5] * dv, acc[i][6] * dv, acc[i][7] * dv);
        float4* gp = (float4*)(d_g + (size_t)r * HID + cg * 8);
        float4* sp = (float4*)(d_S + (size_t)r * HID + cg * 8);
        gp[0] = o0; gp[1] = o1;
        sp[0] = o0; sp[1] = o1;
    }
}

// Scatter: S[c] += g[r] per edge.  16 threads per edge (one float4 each) ->
// coalesced 256B gather of g[r] and consecutive-address atomics into S[c].
__global__ __launch_bounds__(256) void k_scatter(int E) {
    int gid = blockIdx.x * blockDim.x + threadIdx.x;
    if (gid >= E * 16) return;
    int e = gid >> 4;
    int j = gid & 15;
    int r = d_edge[e];
    int c = d_edge[E + e];
    float4 v = ((const float4*)d_g)[r * 16 + j];
    float* s = d_S + (size_t)c * HID + j * 4;
    atomicAdd(s + 0, v.x);
    atomicAdd(s + 1, v.y);
    atomicAdd(s + 2, v.z);
    atomicAdd(s + 3, v.w);
}

// Epilogue: pre = dinv[i]*S[i] + b_conv; relu; JAX partitionable-threefry dropout;
// @ W_lin + b_lin.  One warp per row; lane handles cols lane and lane+32.
__global__ __launch_bounds__(256) void k_final(const float* __restrict__ bc,
                                               const float* __restrict__ Wl,
                                               const float* __restrict__ bl,
                                               float* __restrict__ out, int n) {
    int i    = (blockIdx.x * blockDim.x + threadIdx.x) >> 5;
    int lane = threadIdx.x & 31;
    if (i >= n) return;

    float di   = d_dinv[i];
    float acc0 = 0.f, acc1 = 0.f;

#pragma unroll
    for (int t = 0; t < 2; t++) {
        int col = lane + t * 32;
        unsigned f = (unsigned)i * 64u + (unsigned)col;

        float a = fmaxf(fmaf(di, d_S[(size_t)i * HID + col], bc[col]), 0.f);
        a = jax_keep(f) ? a * 2.f : 0.f;

        acc0 = fmaf(a, Wl[col * 2 + 0], acc0);
        acc1 = fmaf(a, Wl[col * 2 + 1], acc1);
    }

#pragma unroll
    for (int off = 16; off > 0; off >>= 1) {
        acc0 += __shfl_xor_sync(0xffffffffu, acc0, off);
        acc1 += __shfl_xor_sync(0xffffffffu, acc1, off);
    }
    if (lane == 0) {
        out[(size_t)i * 2 + 0] = acc0 + bl[0];
        out[(size_t)i * 2 + 1] = acc1 + bl[1];
    }
}

// ---------------- launch ----------------------------------------------------------
extern "C" void kernel_launch(void* const* d_in, const int* in_sizes, int n_in,
                              void* d_out, int out_size) {
    const float* x  = (const float*)d_in[0];
    const void*  ei = d_in[1];
    const float* Wc = (const float*)d_in[2];
    const float* bc = (const float*)d_in[3];
    const float* Wl = (const float*)d_in[4];
    const float* bl = (const float*)d_in[5];
    float* out = (float*)d_out;

    int n = in_sizes[0] / IND;   // 100000
    int E = in_sizes[1] / 2;     // 1600000 (element count same for i32/i64)

    k_detect<<<1, 256>>>((const unsigned*)ei);
    k_convert<<<(2 * E + 255) / 256, 256>>>(ei, 2 * E);
    k_initdeg<<<(n + 255) / 256, 256>>>(n);
    k_degree<<<(E + 255) / 256, 256>>>(E);
    k_dinv<<<(n + 255) / 256, 256>>>(n);
    k_gemm<<<(n + 127) / 128, 256>>>(x, Wc, n);
    k_scatter<<<(E * 16 + 255) / 256, 256>>>(E);
    k_final<<<(n * 32 + 255) / 256, 256>>>(bc, Wl, bl, out, n);
}

// round 4
// speedup vs baseline: 1.9527x; 1.9527x over previous
#include <cuda_runtime.h>
#include <cstdint>

#define MAXN 100000
#define MAXE 1600000
#define IND 128
#define HID 64
#define NB_SCAN 512   // max scan blocks supported by k_scanB

// ---------------- scratch (device globals; no allocation allowed) ----------------
__device__ int   d_is64;
__device__ int   d_edge[2 * MAXE];          // normalized int32 edge index [2][E]
__device__ int   d_deg[MAXN];               // edge-only in-degree of dst
__device__ float d_dinv[MAXN];
__device__ float d_g[(size_t)MAXN * HID];   // (x@W) * dinv[row]
__device__ int   d_rowptr[MAXN + 1];
__device__ int   d_cursor[MAXN];
__device__ int   d_srcs[MAXE];              // CSR source lists grouped by dst
__device__ int   d_bsum[NB_SCAN];
__device__ int   d_boff[NB_SCAN];

// ---------------- threefry-2x32 (JAX partitionable PRNG, key=(0,42)) --------------
__device__ __forceinline__ void tf_round(unsigned& a, unsigned& b, int r) {
    a += b;
    b = __funnelshift_l(b, b, r);
    b ^= a;
}

__device__ __forceinline__ void threefry2x32(unsigned k0, unsigned k1,
                                             unsigned& x0, unsigned& x1) {
    unsigned k2 = k0 ^ k1 ^ 0x1BD11BDAu;
    x0 += k0; x1 += k1;
    tf_round(x0, x1, 13); tf_round(x0, x1, 15); tf_round(x0, x1, 26); tf_round(x0, x1, 6);
    x0 += k1; x1 += k2 + 1u;
    tf_round(x0, x1, 17); tf_round(x0, x1, 29); tf_round(x0, x1, 16); tf_round(x0, x1, 24);
    x0 += k2; x1 += k0 + 2u;
    tf_round(x0, x1, 13); tf_round(x0, x1, 15); tf_round(x0, x1, 26); tf_round(x0, x1, 6);
    x0 += k0; x1 += k1 + 3u;
    tf_round(x0, x1, 17); tf_round(x0, x1, 29); tf_round(x0, x1, 16); tf_round(x0, x1, 24);
    x0 += k1; x1 += k2 + 4u;
    tf_round(x0, x1, 13); tf_round(x0, x1, 15); tf_round(x0, x1, 26); tf_round(x0, x1, 6);
    x0 += k2; x1 += k0 + 5u;
}

// keep <=> bit31 of (out0 ^ out1) == 0, counter = (0, flat_index)
__device__ __forceinline__ bool jax_keep(unsigned f) {
    unsigned x0 = 0u, x1 = f;
    threefry2x32(0u, 42u, x0, x1);
    return ((x0 ^ x1) >> 31) == 0u;
}

// ---------------- f32x2 packed math (Blackwell) -----------------------------------
__device__ __forceinline__ unsigned long long pack2(float x, float y) {
    unsigned long long r;
    asm("mov.b64 %0, {%1, %2};" : "=l"(r) : "f"(x), "f"(y));
    return r;
}
__device__ __forceinline__ void unpack2(unsigned long long v, float& x, float& y) {
    asm("mov.b64 {%0, %1}, %2;" : "=f"(x), "=f"(y) : "l"(v));
}
__device__ __forceinline__ void ffma2(unsigned long long& d, unsigned long long a,
                                      unsigned long long b) {
    asm("fma.rn.f32x2 %0, %1, %2, %0;" : "+l"(d) : "l"(a), "l"(b));
}

// ---------------- kernels ---------------------------------------------------------
// Detect int64 vs int32 edge_index (int64 LE high words are all 0 for ids < 2^31).
__global__ void k_detect(const unsigned* __restrict__ p) {
    __shared__ int any;
    if (threadIdx.x == 0) any = 0;
    __syncthreads();
    if (threadIdx.x < 128) {
        unsigned v = p[1 + 2 * threadIdx.x];
        if (v != 0u) atomicExch(&any, 1);
    }
    __syncthreads();
    if (threadIdx.x == 0) d_is64 = (any == 0) ? 1 : 0;
}

__global__ void k_zero(int n) {
    int i = blockIdx.x * blockDim.x + threadIdx.x;
    if (i < n) d_deg[i] = 0;
}

// Fused: normalize edge index to int32 AND count in-degree on the dst half.
__global__ void k_convert_degree(const void* __restrict__ p, int E) {
    int i = blockIdx.x * blockDim.x + threadIdx.x;
    if (i >= 2 * E) return;
    int v;
    if (d_is64) v = (int)((const long long*)p)[i];
    else        v = ((const int*)p)[i];
    d_edge[i] = v;
    if (i >= E) atomicAdd(&d_deg[v], 1);
}

__global__ void k_dinv(int n) {
    int i = blockIdx.x * blockDim.x + threadIdx.x;
    if (i < n) d_dinv[i] = rsqrtf((float)(d_deg[i] + 1));   // +1 self loop
}

// Exclusive scan of d_deg -> d_rowptr, three phases.
__global__ void k_scanA(int n) {
    __shared__ int s[256];
    int tid = threadIdx.x;
    int i = blockIdx.x * 256 + tid;
    int v = (i < n) ? d_deg[i] : 0;
    s[tid] = v;
    __syncthreads();
#pragma unroll
    for (int off = 1; off < 256; off <<= 1) {
        int t = (tid >= off) ? s[tid - off] : 0;
        __syncthreads();
        s[tid] += t;
        __syncthreads();
    }
    if (i < n) d_rowptr[i] = s[tid] - v;        // block-local exclusive
    if (tid == 255) d_bsum[blockIdx.x] = s[255];
}

__global__ void k_scanB(int nb) {
    __shared__ int s[NB_SCAN];
    int tid = threadIdx.x;
    s[tid] = (tid < nb) ? d_bsum[tid] : 0;
    __syncthreads();
#pragma unroll
    for (int off = 1; off < NB_SCAN; off <<= 1) {
        int t = (tid >= off) ? s[tid - off] : 0;
        __syncthreads();
        s[tid] += t;
        __syncthreads();
    }
    d_boff[tid] = (tid == 0) ? 0 : s[tid - 1];  // exclusive block offsets
}

__global__ void k_scanC(int n, int E) {
    int i = blockIdx.x * blockDim.x + threadIdx.x;
    if (i < n) {
        int val = d_rowptr[i] + d_boff[i >> 8];
        d_rowptr[i] = val;
        d_cursor[i] = val;
    }
    if (i == 0) d_rowptr[n] = E;
}

// Bucket edges by destination: d_srcs[rowptr[c] .. rowptr[c+1]) = sources of c.
__global__ void k_fill(int E) {
    int e = blockIdx.x * blockDim.x + threadIdx.x;
    if (e >= E) return;
    int r = d_edge[e];
    int c = d_edge[E + e];
    int pos = atomicAdd(&d_cursor[c], 1);
    d_srcs[pos] = r;
}

// g = (x @ W) * dinv[row]  via packed f32x2 FMAs.
// block = 256 threads -> 128 rows; thread computes 4 rows x 8 cols (4 col pairs).
__global__ __launch_bounds__(256) void k_gemm(const float* __restrict__ x,
                                              const float* __restrict__ W,
                                              int n) {
    __shared__ float sW[IND * HID];
    for (int t = threadIdx.x; t < (IND * HID) / 4; t += 256)
        ((float4*)sW)[t] = ((const float4*)W)[t];
    __syncthreads();

    int cg   = threadIdx.x & 7;      // cols cg*8 .. cg*8+7
    int rl   = threadIdx.x >> 3;     // 0..31
    int row0 = blockIdx.x * 128 + rl * 4;

    const float* px[4];
#pragma unroll
    for (int i = 0; i < 4; i++) {
        int r = row0 + i; if (r >= n) r = n - 1;
        px[i] = x + (size_t)r * IND;
    }

    unsigned long long acc[4][4];
#pragma unroll
    for (int i = 0; i < 4; i++)
#pragma unroll
        for (int j = 0; j < 4; j++) acc[i][j] = 0ull;

    for (int k0 = 0; k0 < IND; k0 += 4) {
        float xr[4][4];
#pragma unroll
        for (int i = 0; i < 4; i++)
            *(float4*)xr[i] = *(const float4*)(px[i] + k0);
#pragma unroll
        for (int kk = 0; kk < 4; kk++) {
            const unsigned long long* wp =
                (const unsigned long long*)(sW + (k0 + kk) * HID + cg * 8);
            unsigned long long w0 = wp[0], w1 = wp[1], w2 = wp[2], w3 = wp[3];
#pragma unroll
            for (int i = 0; i < 4; i++) {
                unsigned long long xx = pack2(xr[i][kk], xr[i][kk]);
                ffma2(acc[i][0], xx, w0);
                ffma2(acc[i][1], xx, w1);
                ffma2(acc[i][2], xx, w2);
                ffma2(acc[i][3], xx, w3);
            }
        }
    }

#pragma unroll
    for (int i = 0; i < 4; i++) {
        int r = row0 + i;
        if (r >= n) break;
        float dv = d_dinv[r];
        float o[8];
#pragma unroll
        for (int j = 0; j < 4; j++) {
            unpack2(acc[i][j], o[2 * j], o[2 * j + 1]);
            o[2 * j] *= dv; o[2 * j + 1] *= dv;
        }
        float4* gp = (float4*)(d_g + (size_t)r * HID + cg * 8);
        gp[0] = make_float4(o[0], o[1], o[2], o[3]);
        gp[1] = make_float4(o[4], o[5], o[6], o[7]);
    }
}

// One warp per node: sum g over in-neighbors (+ self), then fused epilogue:
// pre = dinv*sum + b_conv; relu; JAX dropout; @ W_lin + b_lin -> out[node][0..1].
// Lane handles cols {2*lane, 2*lane+1} (one float2 per lane -> 256B/warp loads).
__global__ __launch_bounds__(256) void k_aggr(const float* __restrict__ bc,
                                              const float* __restrict__ Wl,
                                              const float* __restrict__ bl,
                                              float* __restrict__ out, int n) {
    int node = (blockIdx.x * blockDim.x + threadIdx.x) >> 5;
    int lane = threadIdx.x & 31;
    if (node >= n) return;

    const float2* g2 = (const float2*)d_g;
    float2 acc = g2[(size_t)node * 32 + lane];   // self loop
    int k   = d_rowptr[node];
    int end = d_rowptr[node + 1];

    for (; k + 4 <= end; k += 4) {
        int r0 = d_srcs[k], r1 = d_srcs[k + 1], r2 = d_srcs[k + 2], r3 = d_srcs[k + 3];
        float2 v0 = g2[(size_t)r0 * 32 + lane];
        float2 v1 = g2[(size_t)r1 * 32 + lane];
        float2 v2 = g2[(size_t)r2 * 32 + lane];
        float2 v3 = g2[(size_t)r3 * 32 + lane];
        acc.x += (v0.x + v1.x) + (v2.x + v3.x);
        acc.y += (v0.y + v1.y) + (v2.y + v3.y);
    }
    for (; k < end; k++) {
        int r = d_srcs[k];
        float2 v = g2[(size_t)r * 32 + lane];
        acc.x += v.x; acc.y += v.y;
    }

    // epilogue
    float di = d_dinv[node];
    int c0 = 2 * lane;
    float a = fmaxf(fmaf(di, acc.x, bc[c0]), 0.f);
    float b = fmaxf(fmaf(di, acc.y, bc[c0 + 1]), 0.f);
    unsigned f0 = (unsigned)node * 64u + (unsigned)c0;
    a = jax_keep(f0)      ? a * 2.f : 0.f;
    b = jax_keep(f0 + 1u) ? b * 2.f : 0.f;

    float4 w = ((const float4*)Wl)[lane];  // Wl[c0][0], Wl[c0][1], Wl[c0+1][0], Wl[c0+1][1]
    float o0 = fmaf(a, w.x, b * w.z);
    float o1 = fmaf(a, w.y, b * w.w);

#pragma unroll
    for (int off = 16; off > 0; off >>= 1) {
        o0 += __shfl_xor_sync(0xffffffffu, o0, off);
        o1 += __shfl_xor_sync(0xffffffffu, o1, off);
    }
    if (lane == 0) {
        out[(size_t)node * 2 + 0] = o0 + bl[0];
        out[(size_t)node * 2 + 1] = o1 + bl[1];
    }
}

// ---------------- launch ----------------------------------------------------------
extern "C" void kernel_launch(void* const* d_in, const int* in_sizes, int n_in,
                              void* d_out, int out_size) {
    const float* x  = (const float*)d_in[0];
    const void*  ei = d_in[1];
    const float* Wc = (const float*)d_in[2];
    const float* bc = (const float*)d_in[3];
    const float* Wl = (const float*)d_in[4];
    const float* bl = (const float*)d_in[5];
    float* out = (float*)d_out;

    int n = in_sizes[0] / IND;   // 100000
    int E = in_sizes[1] / 2;     // 1600000
    int nb = (n + 255) / 256;    // 391 scan blocks (<= NB_SCAN)

    k_detect<<<1, 256>>>((const unsigned*)ei);
    k_zero<<<nb, 256>>>(n);
    k_convert_degree<<<(2 * E + 255) / 256, 256>>>(ei, E);
    k_dinv<<<nb, 256>>>(n);
    k_scanA<<<nb, 256>>>(n);
    k_scanB<<<1, NB_SCAN>>>(nb);
    k_scanC<<<nb, 256>>>(n, E);
    k_gemm<<<(n + 127) / 128, 256>>>(x, Wc, n);
    k_fill<<<(E + 255) / 256, 256>>>(E);
    k_aggr<<<(n * 32 + 255) / 256, 256>>>(bc, Wl, bl, out, n);
}

// round 6
// speedup vs baseline: 2.2337x; 1.1439x over previous
#include <cuda_runtime.h>
#include <cstdint>

#define MAXN 100000
#define MAXE 1600000
#define IND 128
#define HID 64
#define NB_SCAN 512   // max scan blocks supported by k_scanB

// ---------------- scratch (device globals; no allocation allowed) ----------------
__device__ int   d_is64;
__device__ int   d_deg[MAXN];               // edge-only in-degree of dst
__device__ float d_dinv[MAXN];
__device__ float d_g[(size_t)MAXN * HID];   // h = x @ W   (unscaled)
__device__ int   d_rowptr[MAXN + 1];
__device__ int   d_cursor[MAXN];
__device__ int   d_srcs[MAXE];              // CSR source lists grouped by dst
__device__ int   d_bsum[NB_SCAN];
__device__ int   d_boff[NB_SCAN];

// ---------------- threefry-2x32 (JAX partitionable PRNG, key=(0,42)) --------------
__device__ __forceinline__ void tf_round(unsigned& a, unsigned& b, int r) {
    a += b;
    b = __funnelshift_l(b, b, r);
    b ^= a;
}

__device__ __forceinline__ void threefry2x32(unsigned k0, unsigned k1,
                                             unsigned& x0, unsigned& x1) {
    unsigned k2 = k0 ^ k1 ^ 0x1BD11BDAu;
    x0 += k0; x1 += k1;
    tf_round(x0, x1, 13); tf_round(x0, x1, 15); tf_round(x0, x1, 26); tf_round(x0, x1, 6);
    x0 += k1; x1 += k2 + 1u;
    tf_round(x0, x1, 17); tf_round(x0, x1, 29); tf_round(x0, x1, 16); tf_round(x0, x1, 24);
    x0 += k2; x1 += k0 + 2u;
    tf_round(x0, x1, 13); tf_round(x0, x1, 15); tf_round(x0, x1, 26); tf_round(x0, x1, 6);
    x0 += k0; x1 += k1 + 3u;
    tf_round(x0, x1, 17); tf_round(x0, x1, 29); tf_round(x0, x1, 16); tf_round(x0, x1, 24);
    x0 += k1; x1 += k2 + 4u;
    tf_round(x0, x1, 13); tf_round(x0, x1, 15); tf_round(x0, x1, 26); tf_round(x0, x1, 6);
    x0 += k2; x1 += k0 + 5u;
}

// keep <=> bit31 of (out0 ^ out1) == 0, counter = (0, flat_index)
__device__ __forceinline__ bool jax_keep(unsigned f) {
    unsigned x0 = 0u, x1 = f;
    threefry2x32(0u, 42u, x0, x1);
    return ((x0 ^ x1) >> 31) == 0u;
}

// ---------------- f32x2 packed math (Blackwell) -----------------------------------
__device__ __forceinline__ unsigned long long pack2(float x, float y) {
    unsigned long long r;
    asm("mov.b64 %0, {%1, %2};" : "=l"(r) : "f"(x), "f"(y));
    return r;
}
__device__ __forceinline__ void unpack2(unsigned long long v, float& x, float& y) {
    asm("mov.b64 {%0, %1}, %2;" : "=f"(x), "=f"(y) : "l"(v));
}
__device__ __forceinline__ void ffma2(unsigned long long& d, unsigned long long a,
                                      unsigned long long b) {
    asm("fma.rn.f32x2 %0, %1, %2, %0;" : "+l"(d) : "l"(a), "l"(b));
}

// ---------------- kernels ---------------------------------------------------------
// Detect int64 vs int32 edge_index (int64 LE high words are all 0 for ids < 2^31).
__global__ void k_detect(const unsigned* __restrict__ p) {
    __shared__ int any;
    if (threadIdx.x == 0) any = 0;
    __syncthreads();
    if (threadIdx.x < 128) {
        unsigned v = p[1 + 2 * threadIdx.x];
        if (v != 0u) atomicExch(&any, 1);
    }
    __syncthreads();
    if (threadIdx.x == 0) d_is64 = (any == 0) ? 1 : 0;
}

// In-degree of destinations, reading dst column straight from the input buffer.
__global__ void k_degree(const int* __restrict__ p, int E) {
    int e = blockIdx.x * blockDim.x + threadIdx.x;
    if (e >= E) return;
    int c = d_is64 ? p[2 * (E + e)] : p[E + e];
    atomicAdd(&d_deg[c], 1);
}

// Exclusive scan of d_deg -> d_rowptr (block-local), plus fused dinv.
__global__ void k_scanA(int n) {
    __shared__ int s[256];
    int tid = threadIdx.x;
    int i = blockIdx.x * 256 + tid;
    int v = (i < n) ? d_deg[i] : 0;
    if (i < n) d_dinv[i] = rsqrtf((float)(v + 1));   // +1 self loop
    s[tid] = v;
    __syncthreads();
#pragma unroll
    for (int off = 1; off < 256; off <<= 1) {
        int t = (tid >= off) ? s[tid - off] : 0;
        __syncthreads();
        s[tid] += t;
        __syncthreads();
    }
    if (i < n) d_rowptr[i] = s[tid] - v;        // block-local exclusive
    if (tid == 255) d_bsum[blockIdx.x] = s[255];
}

__global__ void k_scanB(int nb) {
    __shared__ int s[NB_SCAN];
    int tid = threadIdx.x;
    s[tid] = (tid < nb) ? d_bsum[tid] : 0;
    __syncthreads();
#pragma unroll
    for (int off = 1; off < NB_SCAN; off <<= 1) {
        int t = (tid >= off) ? s[tid - off] : 0;
        __syncthreads();
        s[tid] += t;
        __syncthreads();
    }
    d_boff[tid] = (tid == 0) ? 0 : s[tid - 1];  // exclusive block offsets
}

__global__ void k_scanC(int n, int E) {
    int i = blockIdx.x * blockDim.x + threadIdx.x;
    if (i < n) {
        int val = d_rowptr[i] + d_boff[i >> 8];
        d_rowptr[i] = val;
        d_cursor[i] = val;
    }
    if (i == 0) d_rowptr[n] = E;
}

// Bucket edges by destination, reading both columns from the input buffer.
__global__ void k_fill(const int* __restrict__ p, int E) {
    int e = blockIdx.x * blockDim.x + threadIdx.x;
    if (e >= E) return;
    int r, c;
    if (d_is64) { r = p[2 * e]; c = p[2 * (E + e)]; }
    else        { r = p[e];     c = p[E + e]; }
    int pos = atomicAdd(&d_cursor[c], 1);
    d_srcs[pos] = r;
}

// h = x @ W  via packed f32x2 FMAs (no dinv -> independent of edge pipeline).
// block = 256 threads -> 128 rows; thread computes 4 rows x 8 cols (4 col pairs).
__global__ __launch_bounds__(256) void k_gemm(const float* __restrict__ x,
                                              const float* __restrict__ W,
                                              int n) {
    __shared__ float sW[IND * HID];
    for (int t = threadIdx.x; t < (IND * HID) / 4; t += 256)
        ((float4*)sW)[t] = ((const float4*)W)[t];
    __syncthreads();

    int cg   = threadIdx.x & 7;      // cols cg*8 .. cg*8+7
    int rl   = threadIdx.x >> 3;     // 0..31
    int row0 = blockIdx.x * 128 + rl * 4;

    const float* px[4];
#pragma unroll
    for (int i = 0; i < 4; i++) {
        int r = row0 + i; if (r >= n) r = n - 1;
        px[i] = x + (size_t)r * IND;
    }

    unsigned long long acc[4][4];
#pragma unroll
    for (int i = 0; i < 4; i++)
#pragma unroll
        for (int j = 0; j < 4; j++) acc[i][j] = 0ull;

    for (int k0 = 0; k0 < IND; k0 += 4) {
        float xr[4][4];
#pragma unroll
        for (int i = 0; i < 4; i++)
            *(float4*)xr[i] = *(const float4*)(px[i] + k0);
#pragma unroll
        for (int kk = 0; kk < 4; kk++) {
            const unsigned long long* wp =
                (const unsigned long long*)(sW + (k0 + kk) * HID + cg * 8);
            unsigned long long w0 = wp[0], w1 = wp[1], w2 = wp[2], w3 = wp[3];
#pragma unroll
            for (int i = 0; i < 4; i++) {
                unsigned long long xx = pack2(xr[i][kk], xr[i][kk]);
                ffma2(acc[i][0], xx, w0);
                ffma2(acc[i][1], xx, w1);
                ffma2(acc[i][2], xx, w2);
                ffma2(acc[i][3], xx, w3);
            }
        }
    }

#pragma unroll
    for (int i = 0; i < 4; i++) {
        int r = row0 + i;
        if (r >= n) break;
        float o[8];
#pragma unroll
        for (int j = 0; j < 4; j++) unpack2(acc[i][j], o[2 * j], o[2 * j + 1]);
        float4* gp = (float4*)(d_g + (size_t)r * HID + cg * 8);
        gp[0] = make_float4(o[0], o[1], o[2], o[3]);
        gp[1] = make_float4(o[4], o[5], o[6], o[7]);
    }
}

// One warp per node: acc = sum_{r in N(i)} h[r]*dinv[r]  (+ self), then epilogue:
// pre = dinv[i]*acc + b_conv; relu; JAX dropout; @ W_lin + b_lin.
__global__ __launch_bounds__(256) void k_aggr(const float* __restrict__ bc,
                                              const float* __restrict__ Wl,
                                              const float* __restrict__ bl,
                                              float* __restrict__ out, int n) {
    int node = (blockIdx.x * blockDim.x + threadIdx.x) >> 5;
    int lane = threadIdx.x & 31;
    if (node >= n) return;

    const float2* g2 = (const float2*)d_g;
    float dn = d_dinv[node];
    float2 v = g2[(size_t)node * 32 + lane];        // self loop
    float2 acc = make_float2(v.x * dn, v.y * dn);

    int k   = d_rowptr[node];
    int end = d_rowptr[node + 1];

    for (; k + 4 <= end; k += 4) {
        int r0 = d_srcs[k], r1 = d_srcs[k + 1], r2 = d_srcs[k + 2], r3 = d_srcs[k + 3];
        float d0 = d_dinv[r0], d1 = d_dinv[r1], d2 = d_dinv[r2], d3 = d_dinv[r3];
        float2 v0 = g2[(size_t)r0 * 32 + lane];
        float2 v1 = g2[(size_t)r1 * 32 + lane];
        float2 v2 = g2[(size_t)r2 * 32 + lane];
        float2 v3 = g2[(size_t)r3 * 32 + lane];
        acc.x = fmaf(v0.x, d0, acc.x); acc.y = fmaf(v0.y, d0, acc.y);
        acc.x = fmaf(v1.x, d1, acc.x); acc.y = fmaf(v1.y, d1, acc.y);
        acc.x = fmaf(v2.x, d2, acc.x); acc.y = fmaf(v2.y, d2, acc.y);
        acc.x = fmaf(v3.x, d3, acc.x); acc.y = fmaf(v3.y, d3, acc.y);
    }
    for (; k < end; k++) {
        int r = d_srcs[k];
        float dr = d_dinv[r];
        float2 vv = g2[(size_t)r * 32 + lane];
        acc.x = fmaf(vv.x, dr, acc.x); acc.y = fmaf(vv.y, dr, acc.y);
    }

    // epilogue
    int c0 = 2 * lane;
    float a = fmaxf(fmaf(dn, acc.x, bc[c0]), 0.f);
    float b = fmaxf(fmaf(dn, acc.y, bc[c0 + 1]), 0.f);
    unsigned f0 = (unsigned)node * 64u + (unsigned)c0;
    a = jax_keep(f0)      ? a * 2.f : 0.f;
    b = jax_keep(f0 + 1u) ? b * 2.f : 0.f;

    float4 w = ((const float4*)Wl)[lane];  // Wl[c0][*], Wl[c0+1][*]
    float o0 = fmaf(a, w.x, b * w.z);
    float o1 = fmaf(a, w.y, b * w.w);

#pragma unroll
    for (int off = 16; off > 0; off >>= 1) {
        o0 += __shfl_xor_sync(0xffffffffu, o0, off);
        o1 += __shfl_xor_sync(0xffffffffu, o1, off);
    }
    if (lane == 0) {
        out[(size_t)node * 2 + 0] = o0 + bl[0];
        out[(size_t)node * 2 + 1] = o1 + bl[1];
    }
}

// ---------------- launch ----------------------------------------------------------
extern "C" void kernel_launch(void* const* d_in, const int* in_sizes, int n_in,
                              void* d_out, int out_size) {
    const float* x  = (const float*)d_in[0];
    const int*   ei = (const int*)d_in[1];
    const float* Wc = (const float*)d_in[2];
    const float* bc = (const float*)d_in[3];
    const float* Wl = (const float*)d_in[4];
    const float* bl = (const float*)d_in[5];
    float* out = (float*)d_out;

    int n = in_sizes[0] / IND;   // 100000
    int E = in_sizes[1] / 2;     // 1600000
    int nb = (n + 255) / 256;    // 391 scan blocks (<= NB_SCAN)

    static cudaStream_t s2 = nullptr;
    static cudaEvent_t evFork = nullptr, evJoin = nullptr;
    static void* degAddr = nullptr;
    if (!s2) {
        cudaStreamCreateWithFlags(&s2, cudaStreamNonBlocking);
        cudaEventCreateWithFlags(&evFork, cudaEventDisableTiming);
        cudaEventCreateWithFlags(&evJoin, cudaEventDisableTiming);
        cudaGetSymbolAddress(&degAddr, d_deg);
    }

    // Fork: GEMM depends only on inputs -> run it on s2 in parallel with the
    // edge pipeline on the capture-origin (legacy) stream.
    cudaEventRecord(evFork, 0);
    cudaStreamWaitEvent(s2, evFork, 0);
    k_gemm<<<(n + 127) / 128, 256, 0, s2>>>(x, Wc, n);
    cudaEventRecord(evJoin, s2);

    // Edge pipeline on the origin stream.
    k_detect<<<1, 256>>>((const unsigned*)ei);
    cudaMemsetAsync(degAddr, 0, (size_t)n * sizeof(int), 0);
    k_degree<<<(E + 255) / 256, 256>>>(ei, E);
    k_scanA<<<nb, 256>>>(n);
    k_scanB<<<1, NB_SCAN>>>(nb);
    k_scanC<<<nb, 256>>>(n, E);
    k_fill<<<(E + 255) / 256, 256>>>(ei, E);

    // Join, then fused aggregation + epilogue.
    cudaStreamWaitEvent(0, evJoin, 0);
    k_aggr<<<(n * 32 + 255) / 256, 256>>>(bc, Wl, bl, out, n);
}

// round 7
// speedup vs baseline: 2.2607x; 1.0121x over previous
#include <cuda_runtime.h>
#include <cstdint>

#define MAXN 100000
#define MAXE 1600000
#define IND 128
#define HID 64
#define NB_SCAN 512   // max scan blocks supported by k_scanB

// ---------------- scratch (device globals; no allocation allowed) ----------------
__device__ int      d_is64;
__device__ int      d_deg[MAXN];               // edge-only in-degree of dst
__device__ float    d_dinv[MAXN];
__device__ float    d_g[(size_t)MAXN * HID];   // h = x @ W   (unscaled)
__device__ int      d_rowptr[MAXN + 1];
__device__ int      d_cursor[MAXN];
__device__ int      d_srcs[MAXE];              // CSR source lists grouped by dst
__device__ int      d_bsum[NB_SCAN];
__device__ int      d_boff[NB_SCAN];
__device__ unsigned d_mask[MAXN * 2];          // dropout keep bits, 64 per node

// ---------------- threefry-2x32 (JAX partitionable PRNG, key=(0,42)) --------------
__device__ __forceinline__ void tf_round(unsigned& a, unsigned& b, int r) {
    a += b;
    b = __funnelshift_l(b, b, r);
    b ^= a;
}

__device__ __forceinline__ void threefry2x32(unsigned k0, unsigned k1,
                                             unsigned& x0, unsigned& x1) {
    unsigned k2 = k0 ^ k1 ^ 0x1BD11BDAu;
    x0 += k0; x1 += k1;
    tf_round(x0, x1, 13); tf_round(x0, x1, 15); tf_round(x0, x1, 26); tf_round(x0, x1, 6);
    x0 += k1; x1 += k2 + 1u;
    tf_round(x0, x1, 17); tf_round(x0, x1, 29); tf_round(x0, x1, 16); tf_round(x0, x1, 24);
    x0 += k2; x1 += k0 + 2u;
    tf_round(x0, x1, 13); tf_round(x0, x1, 15); tf_round(x0, x1, 26); tf_round(x0, x1, 6);
    x0 += k0; x1 += k1 + 3u;
    tf_round(x0, x1, 17); tf_round(x0, x1, 29); tf_round(x0, x1, 16); tf_round(x0, x1, 24);
    x0 += k1; x1 += k2 + 4u;
    tf_round(x0, x1, 13); tf_round(x0, x1, 15); tf_round(x0, x1, 26); tf_round(x0, x1, 6);
    x0 += k2; x1 += k0 + 5u;
}

// keep <=> bit31 of (out0 ^ out1) == 0, counter = (0, flat_index)
__device__ __forceinline__ bool jax_keep(unsigned f) {
    unsigned x0 = 0u, x1 = f;
    threefry2x32(0u, 42u, x0, x1);
    return ((x0 ^ x1) >> 31) == 0u;
}

// ---------------- f32x2 packed math (Blackwell) -----------------------------------
__device__ __forceinline__ unsigned long long pack2(float x, float y) {
    unsigned long long r;
    asm("mov.b64 %0, {%1, %2};" : "=l"(r) : "f"(x), "f"(y));
    return r;
}
__device__ __forceinline__ void unpack2(unsigned long long v, float& x, float& y) {
    asm("mov.b64 {%0, %1}, %2;" : "=f"(x), "=f"(y) : "l"(v));
}
__device__ __forceinline__ void ffma2(unsigned long long& d, unsigned long long a,
                                      unsigned long long b) {
    asm("fma.rn.f32x2 %0, %1, %2, %0;" : "+l"(d) : "l"(a), "l"(b));
}

// ---------------- kernels ---------------------------------------------------------
// Detect int64 vs int32 edge_index (int64 LE high words are all 0 for ids < 2^31).
__global__ void k_detect(const unsigned* __restrict__ p) {
    __shared__ int any;
    if (threadIdx.x == 0) any = 0;
    __syncthreads();
    if (threadIdx.x < 128) {
        unsigned v = p[1 + 2 * threadIdx.x];
        if (v != 0u) atomicExch(&any, 1);
    }
    __syncthreads();
    if (threadIdx.x == 0) d_is64 = (any == 0) ? 1 : 0;
}

// In-degree of destinations, reading dst column straight from the input buffer.
__global__ void k_degree(const int* __restrict__ p, int E) {
    int e = blockIdx.x * blockDim.x + threadIdx.x;
    if (e >= E) return;
    int c;
    if (d_is64) c = (int)((const long long*)p)[E + e];
    else        c = p[E + e];
    atomicAdd(&d_deg[c], 1);
}

// Exclusive scan of d_deg -> d_rowptr (block-local), plus fused dinv.
__global__ void k_scanA(int n) {
    __shared__ int s[256];
    int tid = threadIdx.x;
    int i = blockIdx.x * 256 + tid;
    int v = (i < n) ? d_deg[i] : 0;
    if (i < n) d_dinv[i] = rsqrtf((float)(v + 1));   // +1 self loop
    s[tid] = v;
    __syncthreads();
#pragma unroll
    for (int off = 1; off < 256; off <<= 1) {
        int t = (tid >= off) ? s[tid - off] : 0;
        __syncthreads();
        s[tid] += t;
        __syncthreads();
    }
    if (i < n) d_rowptr[i] = s[tid] - v;        // block-local exclusive
    if (tid == 255) d_bsum[blockIdx.x] = s[255];
}

__global__ void k_scanB(int nb) {
    __shared__ int s[NB_SCAN];
    int tid = threadIdx.x;
    s[tid] = (tid < nb) ? d_bsum[tid] : 0;
    __syncthreads();
#pragma unroll
    for (int off = 1; off < NB_SCAN; off <<= 1) {
        int t = (tid >= off) ? s[tid - off] : 0;
        __syncthreads();
        s[tid] += t;
        __syncthreads();
    }
    d_boff[tid] = (tid == 0) ? 0 : s[tid - 1];  // exclusive block offsets
}

__global__ void k_scanC(int n, int E) {
    int i = blockIdx.x * blockDim.x + threadIdx.x;
    if (i < n) {
        int val = d_rowptr[i] + d_boff[i >> 8];
        d_rowptr[i] = val;
        d_cursor[i] = val;
    }
    if (i == 0) d_rowptr[n] = E;
}

// Bucket edges by destination, reading both columns from the input buffer.
__global__ void k_fill(const int* __restrict__ p, int E) {
    int e = blockIdx.x * blockDim.x + threadIdx.x;
    if (e >= E) return;
    int r, c;
    if (d_is64) {
        const long long* q = (const long long*)p;
        r = (int)q[e]; c = (int)q[E + e];
    } else {
        r = p[e]; c = p[E + e];
    }
    int pos = atomicAdd(&d_cursor[c], 1);
    d_srcs[pos] = r;
}

// Dropout keep-bit mask, packed 32 bits per warp via ballot.  Depends on nothing.
__global__ void k_mask(int total) {   // total = n * 64, multiple of 32
    int t = blockIdx.x * blockDim.x + threadIdx.x;
    bool kp = (t < total) ? jax_keep((unsigned)t) : false;
    unsigned b = __ballot_sync(0xffffffffu, kp);
    if ((threadIdx.x & 31) == 0 && t < total) d_mask[t >> 5] = b;
}

// h = x @ W  via packed f32x2 FMAs (no dinv -> independent of edge pipeline).
__global__ __launch_bounds__(256) void k_gemm(const float* __restrict__ x,
                                              const float* __restrict__ W,
                                              int n) {
    __shared__ float sW[IND * HID];
    for (int t = threadIdx.x; t < (IND * HID) / 4; t += 256)
        ((float4*)sW)[t] = ((const float4*)W)[t];
    __syncthreads();

    int cg   = threadIdx.x & 7;      // cols cg*8 .. cg*8+7
    int rl   = threadIdx.x >> 3;     // 0..31
    int row0 = blockIdx.x * 128 + rl * 4;

    const float* px[4];
#pragma unroll
    for (int i = 0; i < 4; i++) {
        int r = row0 + i; if (r >= n) r = n - 1;
        px[i] = x + (size_t)r * IND;
    }

    unsigned long long acc[4][4];
#pragma unroll
    for (int i = 0; i < 4; i++)
#pragma unroll
        for (int j = 0; j < 4; j++) acc[i][j] = 0ull;

    for (int k0 = 0; k0 < IND; k0 += 4) {
        float xr[4][4];
#pragma unroll
        for (int i = 0; i < 4; i++)
            *(float4*)xr[i] = *(const float4*)(px[i] + k0);
#pragma unroll
        for (int kk = 0; kk < 4; kk++) {
            const unsigned long long* wp =
                (const unsigned long long*)(sW + (k0 + kk) * HID + cg * 8);
            unsigned long long w0 = wp[0], w1 = wp[1], w2 = wp[2], w3 = wp[3];
#pragma unroll
            for (int i = 0; i < 4; i++) {
                unsigned long long xx = pack2(xr[i][kk], xr[i][kk]);
                ffma2(acc[i][0], xx, w0);
                ffma2(acc[i][1], xx, w1);
                ffma2(acc[i][2], xx, w2);
                ffma2(acc[i][3], xx, w3);
            }
        }
    }

#pragma unroll
    for (int i = 0; i < 4; i++) {
        int r = row0 + i;
        if (r >= n) break;
        float o[8];
#pragma unroll
        for (int j = 0; j < 4; j++) unpack2(acc[i][j], o[2 * j], o[2 * j + 1]);
        float4* gp = (float4*)(d_g + (size_t)r * HID + cg * 8);
        gp[0] = make_float4(o[0], o[1], o[2], o[3]);
        gp[1] = make_float4(o[4], o[5], o[6], o[7]);
    }
}

// Two nodes per warp: lanes 0-15 -> node w, lanes 16-31 -> node w + ceil(n/2).
// Each lane holds one float4 (4 cols). Gathers are predicated on a safe index so
// both halves issue 4 independent LDG.128 per unroll step (8 in flight per warp).
__global__ __launch_bounds__(256) void k_aggr(const float* __restrict__ bc,
                                              const float* __restrict__ Wl,
                                              const float* __restrict__ bl,
                                              float* __restrict__ out, int n) {
    int warp = (blockIdx.x * blockDim.x + threadIdx.x) >> 5;
    int lane = threadIdx.x & 31;
    int l16  = lane & 15;
    int hf   = lane >> 4;
    int halfn = (n + 1) >> 1;
    if (warp >= halfn) return;

    int node = hf ? warp + halfn : warp;
    bool valid = node < n;
    if (!valid) node = warp;          // safe duplicate for the dangling half

    const float4* g4 = (const float4*)d_g;
    float dn = d_dinv[node];
    float4 acc = g4[(size_t)node * 16 + l16];     // self loop
    acc.x *= dn; acc.y *= dn; acc.z *= dn; acc.w *= dn;

    int k   = d_rowptr[node];
    int end = d_rowptr[node + 1];

    while (__any_sync(0xffffffffu, k < end)) {
#pragma unroll
        for (int j = 0; j < 4; j++) {
            int idx = k + j;
            bool p = idx < end;
            int r = p ? d_srcs[idx] : node;       // safe index, same L2 line when idle
            float dr = d_dinv[r];
            float4 v = g4[(size_t)r * 16 + l16];
            if (p) {
                acc.x = fmaf(v.x, dr, acc.x);
                acc.y = fmaf(v.y, dr, acc.y);
                acc.z = fmaf(v.z, dr, acc.z);
                acc.w = fmaf(v.w, dr, acc.w);
            }
        }
        k += 4;
    }

    // epilogue: bias + relu + precomputed dropout mask + 64->2 projection
    int c0 = 4 * l16;
    float4 bb = ((const float4*)bc)[l16];
    float a0 = fmaxf(fmaf(dn, acc.x, bb.x), 0.f);
    float a1 = fmaxf(fmaf(dn, acc.y, bb.y), 0.f);
    float a2 = fmaxf(fmaf(dn, acc.z, bb.z), 0.f);
    float a3 = fmaxf(fmaf(dn, acc.w, bb.w), 0.f);

    unsigned mw = d_mask[node * 2 + (l16 >> 3)];
    unsigned sh = (unsigned)(c0 & 31);
    a0 = ((mw >> sh) & 1u)        ? a0 * 2.f : 0.f;
    a1 = ((mw >> (sh + 1)) & 1u)  ? a1 * 2.f : 0.f;
    a2 = ((mw >> (sh + 2)) & 1u)  ? a2 * 2.f : 0.f;
    a3 = ((mw >> (sh + 3)) & 1u)  ? a3 * 2.f : 0.f;

    float4 wA = ((const float4*)Wl)[2 * l16];      // rows c0, c0+1
    float4 wB = ((const float4*)Wl)[2 * l16 + 1];  // rows c0+2, c0+3
    float o0 = fmaf(a0, wA.x, fmaf(a1, wA.z, fmaf(a2, wB.x, a3 * wB.z)));
    float o1 = fmaf(a0, wA.y, fmaf(a1, wA.w, fmaf(a2, wB.y, a3 * wB.w)));

#pragma unroll
    for (int off = 8; off > 0; off >>= 1) {        // reduce within each half-warp
        o0 += __shfl_xor_sync(0xffffffffu, o0, off);
        o1 += __shfl_xor_sync(0xffffffffu, o1, off);
    }
    if (l16 == 0 && valid) {
        out[(size_t)node * 2 + 0] = o0 + bl[0];
        out[(size_t)node * 2 + 1] = o1 + bl[1];
    }
}

// ---------------- launch ----------------------------------------------------------
extern "C" void kernel_launch(void* const* d_in, const int* in_sizes, int n_in,
                              void* d_out, int out_size) {
    const float* x  = (const float*)d_in[0];
    const int*   ei = (const int*)d_in[1];
    const float* Wc = (const float*)d_in[2];
    const float* bc = (const float*)d_in[3];
    const float* Wl = (const float*)d_in[4];
    const float* bl = (const float*)d_in[5];
    float* out = (float*)d_out;

    int n = in_sizes[0] / IND;   // 100000
    int E = in_sizes[1] / 2;     // 1600000
    int nb = (n + 255) / 256;    // 391 scan blocks (<= NB_SCAN)

    static cudaStream_t s2 = nullptr;
    static cudaEvent_t evFork = nullptr, evJoin = nullptr;
    static void* degAddr = nullptr;
    if (!s2) {
        cudaStreamCreateWithFlags(&s2, cudaStreamNonBlocking);
        cudaEventCreateWithFlags(&evFork, cudaEventDisableTiming);
        cudaEventCreateWithFlags(&evJoin, cudaEventDisableTiming);
        cudaGetSymbolAddress(&degAddr, d_deg);
    }

    // Fork: GEMM + dropout mask depend only on inputs -> run on s2 in parallel
    // with the edge pipeline on the capture-origin stream.
    cudaEventRecord(evFork, 0);
    cudaStreamWaitEvent(s2, evFork, 0);
    k_gemm<<<(n + 127) / 128, 256, 0, s2>>>(x, Wc, n);
    k_mask<<<(n * 64 + 255) / 256, 256, 0, s2>>>(n * 64);
    cudaEventRecord(evJoin, s2);

    // Edge pipeline on the origin stream.
    k_detect<<<1, 256>>>((const unsigned*)ei);
    cudaMemsetAsync(degAddr, 0, (size_t)n * sizeof(int), 0);
    k_degree<<<(E + 255) / 256, 256>>>(ei, E);
    k_scanA<<<nb, 256>>>(n);
    k_scanB<<<1, NB_SCAN>>>(nb);
    k_scanC<<<nb, 256>>>(n, E);
    k_fill<<<(E + 255) / 256, 256>>>(ei, E);

    // Join, then fused aggregation + epilogue.
    cudaStreamWaitEvent(0, evJoin, 0);
    int halfn = (n + 1) / 2;
    k_aggr<<<(halfn * 32 + 255) / 256, 256>>>(bc, Wl, bl, out, n);
}